// round 16
// baseline (speedup 1.0000x reference)
#include <cuda_runtime.h>
#include <math.h>
#include <stdint.h>

#define KNUM 512
#define DDIM 64
#define NROWS 65536
#define HW 4096
#define NB 16
#define MTILE 64
#define NTILES 1024          // NROWS / MTILE
#define THREADS 256
#define GRID 608
#define CAP 16

typedef unsigned long long ull;

// ---------------- device scratch ----------------
__device__ double g_loss_sum;
__device__ unsigned int g_counts[KNUM];
__device__ unsigned int g_done;
__device__ unsigned int g_ticket;
__device__ float ssq_g[KNUM];
__device__ float invsk_g[KNUM];
__device__ unsigned int g_SeMax_bits;     // monotone atomicMax, idempotent across replays
__device__ unsigned int g_invskMax_bits;
// paired s8 B fragments: bpack_g[p][(k*4+q)*2+h]; p=0: k-dims 0..31, p=1: 32..63
__device__ uint32_t bpack_g[2][KNUM * 8];

// ---------------- smem layout (bytes): total 56864 -> 4 CTAs/SM -------------
#define B0_OFF    0        // 16384
#define B1_OFF    16384    // 16384
#define XS_OFF    32768    // 64 rows * 64 c * 4 = 16384   x_s[c*64+row]
#define SSQ_OFF   49152    // 2048
#define INVSK_OFF 51200    // 2048
#define CL_OFF    53248    // 64*CAP*2 = 2048 (u16)
#define SLOT_OFF  55296    // 64*8 = 512
#define CC_OFF    55808    // 256
#define SX_OFF    56064    // 256
#define SR_OFF    56320    // 256
#define MRG_OFF   56576    // 256
#define WS_OFF    56832    // 32
#define SMEM_TOTAL 56864
#define FIN_OFF   XS_OFF   // finalize overlay: 512 doubles = 4096 over x_s

__device__ __forceinline__ void imma16832(int d[4], const uint32_t a[4],
                                          uint32_t b0, uint32_t b1) {
    asm volatile(
        "mma.sync.aligned.m16n8k32.row.col.s32.s8.s8.s32 "
        "{%0,%1,%2,%3}, {%4,%5,%6,%7}, {%8,%9}, {%0,%1,%2,%3};"
        : "+r"(d[0]), "+r"(d[1]), "+r"(d[2]), "+r"(d[3])
        : "r"(a[0]), "r"(a[1]), "r"(a[2]), "r"(a[3]), "r"(b0), "r"(b1));
}

__device__ __forceinline__ uint32_t pack_s8x4(int v0, int v1, int v2, int v3) {
    return (uint32_t)(v0 & 255) | ((uint32_t)(v1 & 255) << 8) |
           ((uint32_t)(v2 & 255) << 16) | ((uint32_t)(v3 & 255) << 24);
}

// ---------------- prep (single kernel): resets + exact ssq + s8 pack --------
__global__ void vq_prep_kernel(const float* __restrict__ emb) {
    const int k = blockIdx.x, t = threadIdx.x;
    if (t == 0) {
        g_counts[k] = 0u;
        if (k == 0) { g_loss_sum = 0.0; g_done = 0u; g_ticket = 0u; }
        const float* e = emb + k * DDIM;
        float s = 0.f;
        for (int d = 0; d < DDIM; d++)
            s = __fadd_rn(s, __fmul_rn(e[d], e[d]));   // reference order (unfused)
        ssq_g[k] = s;
    }
    // per-code max|e|
    float a = fmaxf(fabsf(emb[k * DDIM + t]), fabsf(emb[k * DDIM + 32 + t]));
    #pragma unroll
    for (int o = 16; o > 0; o >>= 1)
        a = fmaxf(a, __shfl_xor_sync(0xffffffffu, a, o));
    float maxe  = fmaxf(a, 1e-30f);
    float sk    = 127.f / maxe;
    float invsk = maxe * (1.f / 127.f);
    int sabs = 0;
    if (t < 16) {
        int w = t >> 2, q = t & 3;
        int d0 = w * 16 + q * 4;
        int v[4];
        #pragma unroll
        for (int j = 0; j < 4; j++) {
            v[j] = __float2int_rn(emb[k * DDIM + d0 + j] * sk);
            sabs += abs(v[j]);
        }
        bpack_g[w >> 1][(k * 4 + q) * 2 + (w & 1)] = pack_s8x4(v[0], v[1], v[2], v[3]);
    }
    #pragma unroll
    for (int o = 16; o > 0; o >>= 1)
        sabs += __shfl_xor_sync(0xffffffffu, sabs, o);
    if (t == 0) {
        invsk_g[k] = invsk;
        atomicMax(&g_SeMax_bits, __float_as_uint((float)sabs * invsk));
        atomicMax(&g_invskMax_bits, __float_as_uint(invsk));
    }
}

// ---------------- exact rescue evaluation (bit-exact reference pipeline) ----
__device__ __forceinline__ void eval_exact(int k, int row, const float* emb,
                                           const float* x_s, const float* sx_s,
                                           const float* ssq_s, ull* slot) {
    const float4* eg = (const float4*)(emb + k * DDIM);
    float acc = 0.f;
    #pragma unroll
    for (int i = 0; i < 16; i++) {
        float4 e = eg[i];
        acc = fmaf(x_s[(4 * i + 0) * MTILE + row], e.x, acc);
        acc = fmaf(x_s[(4 * i + 1) * MTILE + row], e.y, acc);
        acc = fmaf(x_s[(4 * i + 2) * MTILE + row], e.z, acc);
        acc = fmaf(x_s[(4 * i + 3) * MTILE + row], e.w, acc);
    }
    float d = __fadd_rn(sx_s[row], ssq_s[k]);
    d = __fsub_rn(d, __fmul_rn(2.0f, acc));
    uint32_t ui = __float_as_uint(d);
    uint32_t key = ui ^ ((ui & 0x80000000u) ? 0xFFFFFFFFu : 0x80000000u);
    atomicMin(&slot[row], ((ull)key << 32) | (uint32_t)k);
}

// ---------------- main: persistent ticketed 256-thread CTAs, 4/SM -----------
extern __shared__ char smem[];

__global__ __launch_bounds__(THREADS, 4)
void vq_main_kernel(const float* __restrict__ z_e,
                    const float* __restrict__ emb,
                    float* __restrict__ zq_out,
                    float* __restrict__ idx_out,
                    float* __restrict__ loss_out,
                    float* __restrict__ perp_out)
{
    const int tid  = threadIdx.x;
    const int wid  = tid >> 5;       // 0..7
    const int lane = tid & 31;
    const int wq   = lane & 3;
    const int wr   = lane >> 2;

    float* x_s     = (float*)(smem + XS_OFF);
    float* ssq_s   = (float*)(smem + SSQ_OFF);
    float* invsk_s = (float*)(smem + INVSK_OFF);
    float* sx_s    = (float*)(smem + SX_OFF);
    float* sr_s    = (float*)(smem + SR_OFF);
    float* mrg_s   = (float*)(smem + MRG_OFF);
    uint16_t* clist = (uint16_t*)(smem + CL_OFF);
    uint32_t* ccnt  = (uint32_t*)(smem + CC_OFF);
    ull*   slot    = (ull*)(smem + SLOT_OFF);
    float* wsum    = (float*)(smem + WS_OFF);
    const uint32_t* sB0 = (const uint32_t*)(smem + B0_OFF);
    const uint32_t* sB1 = (const uint32_t*)(smem + B1_OFF);
    __shared__ unsigned s_tile;
    __shared__ int s_final;

    // Stage B + per-code scalars once per CTA
    {
        const uint4* g0 = (const uint4*)bpack_g[0];
        const uint4* g1 = (const uint4*)bpack_g[1];
        uint4* h0 = (uint4*)(smem + B0_OFF);
        uint4* h1 = (uint4*)(smem + B1_OFF);
        for (int i = tid; i < KNUM * 2; i += THREADS) { h0[i] = g0[i]; h1[i] = g1[i]; }
    }
    for (int i = tid; i < KNUM; i += THREADS) {
        ssq_s[i]   = ssq_g[i];
        invsk_s[i] = invsk_g[i];
    }
    if (tid == 0) s_final = 0;

    const float SeMax    = __uint_as_float(g_SeMax_bits);
    const float invSkMax = __uint_as_float(g_invskMax_bits);

    for (;;) {
        __syncthreads();
        if (tid == 0) s_tile = atomicAdd(&g_ticket, 1u);
        __syncthreads();
        const unsigned tile = s_tile;
        if (tile >= NTILES) break;

        const int n   = tile >> 6;              // 64 tiles per batch image
        const int hw0 = (tile & 63) * MTILE;
        const size_t gbase = (size_t)n * (DDIM * HW) + hw0;

        if (tid < MTILE) { slot[tid] = ~0ull; ccnt[tid] = 0u; }
        // x tile (coalesced 256B rows) -> x_s[c*64+row]
        for (int i = tid; i < MTILE * DDIM; i += THREADS) {
            int c = i >> 6, r = i & 63;
            x_s[c * MTILE + r] = z_e[gbase + (size_t)c * HW + r];
        }
        __syncthreads();

        // per-row: exact ||x||^2 (reference order) + max|x| + sum|x|
        if (tid < MTILE) {
            float s = 0.f, mx = 1e-30f, sa = 0.f;
            for (int c = 0; c < DDIM; c++) {
                float xv = x_s[c * MTILE + tid];
                s = __fadd_rn(s, __fmul_rn(xv, xv));
                float av = fabsf(xv);
                mx = fmaxf(mx, av);
                sa += av;
            }
            sx_s[tid]  = s;
            float srinv = mx * (1.f / 127.f);
            sr_s[tid]  = __fdividef(127.f, mx);
            mrg_s[tid] = srinv * SeMax + invSkMax * sa + 5e-5f;
        }
        __syncthreads();

        // s8 A fragments for this warp's 16 rows (rA, rB)
        const int r0   = (wid & 3) * 16;
        const int half = wid >> 2;          // cols half*256 .. +255
        const int rA = r0 + wr, rB = rA + 8;
        const float srAq = sr_s[rA], srBq = sr_s[rB];
        uint32_t aq[2][4];
        #pragma unroll
        for (int kh = 0; kh < 2; kh++) {
            #pragma unroll
            for (int hh = 0; hh < 2; hh++) {
                int d0 = kh * 32 + hh * 16 + wq * 4;
                int vA[4], vB[4];
                #pragma unroll
                for (int j = 0; j < 4; j++) {
                    vA[j] = __float2int_rn(x_s[(d0 + j) * MTILE + rA] * srAq);
                    vB[j] = __float2int_rn(x_s[(d0 + j) * MTILE + rB] * srBq);
                }
                aq[kh][hh * 2 + 0] = pack_s8x4(vA[0], vA[1], vA[2], vA[3]);
                aq[kh][hh * 2 + 1] = pack_s8x4(vB[0], vB[1], vB[2], vB[3]);
            }
        }
        const float srinvA = 127.f / fmaxf(srAq * 127.f, 1e-30f) * 127.f; // unused guard
        const float sriA = mrg_s[rA] * 0.f + (1.f / 127.f) * (127.f / srAq); // == max|x_rA|/127
        const float sriB = (1.f / 127.f) * (127.f / srBq);
        const float crowA = -2.f * sriA, crowB = -2.f * sriB;
        const float mrgA  = mrg_s[rA],  mrgB  = mrg_s[rB];

        // IMMA filter: 8 groups of 32 cols
        float m0 = 3.4e38f, m1 = 3.4e38f;
        for (int g = 0; g < 8; g++) {
            int acc[4][4];
            #pragma unroll
            for (int nf = 0; nf < 4; nf++)
                #pragma unroll
                for (int j = 0; j < 4; j++) acc[nf][j] = 0;

            const int colbase0 = half * 256 + g * 32;
            #pragma unroll
            for (int nf = 0; nf < 4; nf++) {
                int bi = ((colbase0 + nf * 8 + wr) << 2) + wq;
                uint2 p01 = *(const uint2*)(sB0 + bi * 2);   // conflict-free LDS.64
                uint2 p23 = *(const uint2*)(sB1 + bi * 2);
                imma16832(acc[nf], aq[0], p01.x, p01.y);
                imma16832(acc[nf], aq[1], p23.x, p23.y);
            }
            float dv[4][4];
            #pragma unroll
            for (int nf = 0; nf < 4; nf++) {
                int c0 = colbase0 + nf * 8 + wq * 2;
                float2 sq = *(const float2*)(ssq_s + c0);
                float2 iv = *(const float2*)(invsk_s + c0);
                dv[nf][0] = fmaf((float)acc[nf][0] * iv.x, crowA, sq.x);
                dv[nf][1] = fmaf((float)acc[nf][1] * iv.y, crowA, sq.y);
                dv[nf][2] = fmaf((float)acc[nf][2] * iv.x, crowB, sq.x);
                dv[nf][3] = fmaf((float)acc[nf][3] * iv.y, crowB, sq.y);
                m0 = fminf(m0, fminf(dv[nf][0], dv[nf][1]));
                m1 = fminf(m1, fminf(dv[nf][2], dv[nf][3]));
            }
            m0 = fminf(m0, __shfl_xor_sync(0xffffffffu, m0, 1));
            m0 = fminf(m0, __shfl_xor_sync(0xffffffffu, m0, 2));
            m1 = fminf(m1, __shfl_xor_sync(0xffffffffu, m1, 1));
            m1 = fminf(m1, __shfl_xor_sync(0xffffffffu, m1, 2));
            float t0 = m0 + mrgA, t1 = m1 + mrgB;
            #pragma unroll
            for (int nf = 0; nf < 4; nf++) {
                int c0 = colbase0 + nf * 8 + wq * 2;
                if (dv[nf][0] <= t0) { uint32_t c = atomicAdd(&ccnt[rA], 1u); if (c < CAP) clist[rA * CAP + c] = (uint16_t)c0; }
                if (dv[nf][1] <= t0) { uint32_t c = atomicAdd(&ccnt[rA], 1u); if (c < CAP) clist[rA * CAP + c] = (uint16_t)(c0 + 1); }
                if (dv[nf][2] <= t1) { uint32_t c = atomicAdd(&ccnt[rB], 1u); if (c < CAP) clist[rB * CAP + c] = (uint16_t)c0; }
                if (dv[nf][3] <= t1) { uint32_t c = atomicAdd(&ccnt[rB], 1u); if (c < CAP) clist[rB * CAP + c] = (uint16_t)(c0 + 1); }
            }
        }
        __syncthreads();

        // Rescue: exact re-evaluation (4 threads per row)
        {
            int row = tid >> 2, e0 = tid & 3;
            int cnt = (int)ccnt[row];
            if (cnt <= CAP) {
                for (int i = e0; i < cnt; i += 4)
                    eval_exact((int)clist[row * CAP + i], row, emb, x_s, sx_s, ssq_s, slot);
            } else {
                for (int k = e0; k < KNUM; k += 4)   // guaranteed-correct fallback
                    eval_exact(k, row, emb, x_s, sx_s, ssq_s, slot);
            }
        }
        __syncthreads();

        // Row-owned z_q straight-through + loss
        float lsum = 0.f;
        if (tid < MTILE) {
            const int r = tid;
            const int kk = (int)(uint32_t)(slot[r] & 0xFFFFFFFFull);
            if (idx_out) idx_out[tile * MTILE + r] = (float)kk;
            atomicAdd(&g_counts[kk], 1u);
            const float4* eg = (const float4*)(emb + kk * DDIM);
            #pragma unroll
            for (int i = 0; i < 16; i++) {
                float4 e = eg[i];
                #pragma unroll
                for (int j = 0; j < 4; j++) {
                    int c = 4 * i + j;
                    float v  = (j == 0) ? e.x : (j == 1) ? e.y : (j == 2) ? e.z : e.w;
                    float xv = x_s[c * MTILE + r];
                    float diff = __fsub_rn(v, xv);
                    zq_out[gbase + (size_t)c * HW + r] = __fadd_rn(xv, diff);
                    lsum = fmaf(diff, diff, lsum);
                }
            }
        }
        #pragma unroll
        for (int o = 16; o > 0; o >>= 1)
            lsum += __shfl_down_sync(0xffffffffu, lsum, o);
        if (lane == 0 && wid < 2) wsum[wid] = lsum;
        __syncthreads();
        if (tid == 0) {
            atomicAdd(&g_loss_sum, (double)(wsum[0] + wsum[1]));
            __threadfence();
            unsigned r = atomicAdd(&g_done, 1u);
            if (r == NTILES - 1) s_final = 1;
        }
    }

    // ---- fused finalize: the CTA that completed the last tile ----
    __syncthreads();
    if (s_final) {
        double* sh = (double*)(smem + FIN_OFF);
        for (int k = tid; k < KNUM; k += THREADS) {
            double c = (double)g_counts[k];
            double p = c / (double)NROWS;
            sh[k] = p * log(p + 1e-10);
        }
        __syncthreads();
        for (int s = KNUM / 2; s >= THREADS; s >>= 1) {
            for (int k = tid; k < s; k += THREADS) sh[k] += sh[k + s];
            __syncthreads();
        }
        for (int s = THREADS / 2; s > 0; s >>= 1) {
            if (tid < s && tid + s < KNUM) sh[tid] += sh[tid + s];
            __syncthreads();
        }
        if (tid == 0) {
            if (perp_out) *perp_out = (float)exp(-sh[0]);
            if (loss_out) *loss_out = (float)(0.25 * g_loss_sum / (double)((size_t)NROWS * DDIM));
        }
    }
}

extern "C" void kernel_launch(void* const* d_in, const int* in_sizes, int n_in,
                              void* d_out, int out_size) {
    const float* z_e = (const float*)d_in[0];
    const float* emb = (const float*)d_in[1];
    float* out = (float*)d_out;

    float* zq_out = out;
    float* loss_p = nullptr;
    float* perp_p = nullptr;
    float* idx_p  = nullptr;
    const int ZQ = NB * DDIM * HW;   // 4194304
    if (out_size >= ZQ + 2 + NROWS) {
        loss_p = out + ZQ;
        perp_p = out + ZQ + 1;
        idx_p  = out + ZQ + 2;
    }

    cudaFuncSetAttribute(vq_main_kernel,
                         cudaFuncAttributeMaxDynamicSharedMemorySize, SMEM_TOTAL);

    vq_prep_kernel<<<KNUM, 32>>>(emb);
    vq_main_kernel<<<GRID, THREADS, SMEM_TOTAL>>>(z_e, emb, zq_out, idx_p, loss_p, perp_p);
}